// round 1
// baseline (speedup 1.0000x reference)
#include <cuda_runtime.h>

// Problem constants
constexpr int BB   = 128;   // batch
constexpr int CC   = 64;    // state channels
constexpr int K1   = 192;   // 3*C perception channels
constexpr int M1   = 512;   // MLP dim
constexpr int HH   = 40;
constexpr int WW   = 40;
constexpr int HWp  = 1600;  // H*W
constexpr float LN_EPS = 1e-5f;

// Scratch (static device arrays; allocation-free per harness rules)
__device__ float g_perc[(size_t)BB * K1 * HWp];        // 157 MB
__device__ float g_y[(size_t)BB * M1 * HWp];           // 419 MB
__device__ float g_part[BB * 100 * 2];                 // per-block partial sums
__device__ float g_stats[BB * 2];                      // mu, rstd per sample

// ---------------------------------------------------------------------------
// Kernel 1: depthwise sobel_x / sobel_y / identity perception
// out channel layout: [b][3c+{0:sx,1:sy,2:id}][p]
// ---------------------------------------------------------------------------
__global__ void perc_kernel(const float* __restrict__ state) {
    int idx = blockIdx.x * blockDim.x + threadIdx.x;
    if (idx >= BB * CC * HWp) return;
    int p  = idx % HWp;
    int bc = idx / HWp;
    int c  = bc % CC;
    int b  = bc / CC;
    int h = p / WW, w = p % WW;
    const float* s = state + (size_t)(b * CC + c) * HWp;
    float v[3][3];
#pragma unroll
    for (int dy = -1; dy <= 1; dy++)
#pragma unroll
        for (int dx = -1; dx <= 1; dx++) {
            int hh = h + dy, ww2 = w + dx;
            v[dy + 1][dx + 1] =
                (hh >= 0 && hh < HH && ww2 >= 0 && ww2 < WW) ? s[hh * WW + ww2] : 0.f;
        }
    float sx = -v[0][0] + v[0][2] - 2.f * v[1][0] + 2.f * v[1][2] - v[2][0] + v[2][2];
    float sy = -v[0][0] - 2.f * v[0][1] - v[0][2] + v[2][0] + 2.f * v[2][1] + v[2][2];
    float id = v[1][1];
    float* o = g_perc + (size_t)(b * K1 + 3 * c) * HWp + p;
    o[0]        = sx;
    o[HWp]      = sy;
    o[2 * HWp]  = id;
}

// ---------------------------------------------------------------------------
// Kernel 2: GEMM1  Y[b] = W1[512,192] @ P[b][192,1600], plus per-tile stats
// Grid: (nt=25, mt=4, b=128). Block 256. BM=128, BN=64, BK=16.
// ---------------------------------------------------------------------------
constexpr int BM1 = 128, BN1 = 64, BK1 = 16;

__global__ __launch_bounds__(256) void gemm1_kernel(const float* __restrict__ w1) {
    int b  = blockIdx.z;
    int mt = blockIdx.y;
    int nt = blockIdx.x;
    __shared__ float As[BK1][BM1];
    __shared__ float Bs[BK1][BN1];
    int tid = threadIdx.x;
    int tx = tid % 16;  // n: 16 * 4 = 64
    int ty = tid / 16;  // m: 16 * 8 = 128
    float acc[8][4] = {};

    const float* Ag = w1 + (size_t)mt * BM1 * K1;
    const float* Bg = g_perc + (size_t)b * K1 * HWp + nt * BN1;

    for (int k0 = 0; k0 < K1; k0 += BK1) {
        // A tile 128x16 (2 float4 per thread), transposed into As[k][m]
#pragma unroll
        for (int i = 0; i < 2; i++) {
            int f4i = tid + i * 256;           // 0..511
            int r   = f4i >> 2;                // 0..127
            int cc  = (f4i & 3) * 4;           // 0,4,8,12
            float4 a = *reinterpret_cast<const float4*>(Ag + r * K1 + k0 + cc);
            As[cc + 0][r] = a.x;
            As[cc + 1][r] = a.y;
            As[cc + 2][r] = a.z;
            As[cc + 3][r] = a.w;
        }
        // B tile 16x64 (1 float4 per thread)
        {
            int r  = tid >> 4;           // 0..15
            int cc = (tid & 15) * 4;     // 0..60
            float4 bv = *reinterpret_cast<const float4*>(Bg + (size_t)(k0 + r) * HWp + cc);
            *reinterpret_cast<float4*>(&Bs[r][cc]) = bv;
        }
        __syncthreads();
#pragma unroll
        for (int k = 0; k < BK1; k++) {
            float ra[8], rb[4];
#pragma unroll
            for (int i = 0; i < 8; i++) ra[i] = As[k][ty * 8 + i];
#pragma unroll
            for (int j = 0; j < 4; j++) rb[j] = Bs[k][tx * 4 + j];
#pragma unroll
            for (int i = 0; i < 8; i++)
#pragma unroll
                for (int j = 0; j < 4; j++) acc[i][j] += ra[i] * rb[j];
        }
        __syncthreads();
    }

    // store Y + accumulate per-thread stats
    float s = 0.f, s2 = 0.f;
    float* Cg = g_y + (size_t)b * M1 * HWp + (size_t)(mt * BM1) * HWp + nt * BN1;
#pragma unroll
    for (int i = 0; i < 8; i++) {
        int m = ty * 8 + i;
        float4 v4 = make_float4(acc[i][0], acc[i][1], acc[i][2], acc[i][3]);
        *reinterpret_cast<float4*>(Cg + (size_t)m * HWp + tx * 4) = v4;
        s  += v4.x + v4.y + v4.z + v4.w;
        s2 += v4.x * v4.x + v4.y * v4.y + v4.z * v4.z + v4.w * v4.w;
    }

    // deterministic block reduction -> partials
    __shared__ float red[256];
    red[tid] = s;
    __syncthreads();
    for (int o = 128; o > 0; o >>= 1) {
        if (tid < o) red[tid] += red[tid + o];
        __syncthreads();
    }
    float bs = red[0];
    __syncthreads();
    red[tid] = s2;
    __syncthreads();
    for (int o = 128; o > 0; o >>= 1) {
        if (tid < o) red[tid] += red[tid + o];
        __syncthreads();
    }
    if (tid == 0) {
        int pi = (b * 4 + mt) * 25 + nt;   // == b*100 + mt*25 + nt
        g_part[pi * 2 + 0] = bs;
        g_part[pi * 2 + 1] = red[0];
    }
}

// ---------------------------------------------------------------------------
// Kernel 3: finalize per-sample mean / rstd (deterministic fixed-order sum)
// ---------------------------------------------------------------------------
__global__ void stats_kernel() {
    int b = threadIdx.x;
    if (b >= BB) return;
    float s = 0.f, s2 = 0.f;
    for (int i = 0; i < 100; i++) {
        s  += g_part[(b * 100 + i) * 2 + 0];
        s2 += g_part[(b * 100 + i) * 2 + 1];
    }
    float inv = 1.f / (float)(M1 * HWp);
    float mu  = s * inv;
    float var = s2 * inv - mu * mu;
    g_stats[b * 2 + 0] = mu;
    g_stats[b * 2 + 1] = rsqrtf(var + LN_EPS);
}

// ---------------------------------------------------------------------------
// Kernel 4: GEMM2  Z = W2[64,512] @ relu(LN(Y)) + epilogue (mask, alive, residual)
// Grid: (nt=25, 1, b=128). Block 256. BM=64, BN=64, BK=32.
// ---------------------------------------------------------------------------
constexpr int BM2 = 64, BN2 = 64, BK2 = 32;

__global__ __launch_bounds__(256) void gemm2_kernel(
    const float* __restrict__ w2, const float* __restrict__ lnw,
    const float* __restrict__ lnb, const float* __restrict__ state,
    const int* __restrict__ mask, float* __restrict__ out) {
    int b  = blockIdx.z;
    int nt = blockIdx.x;
    __shared__ float As[BK2][BM2];
    __shared__ float Bs[BK2][BN2];
    __shared__ float scl[BN2];
    int tid = threadIdx.x;
    int tx = tid % 16;  // n: 16*4 = 64
    int ty = tid / 16;  // m: 16*4 = 64

    float mu   = g_stats[b * 2 + 0];
    float rstd = g_stats[b * 2 + 1];

    // per-column update scale: mask[p] * (maxpool3x3(state[:,3]) > 0.1)
    if (tid < BN2) {
        int p = nt * BN2 + tid;
        int h = p / WW, w = p % WW;
        const float* alive = state + ((size_t)b * CC + 3) * HWp;
        float mx = -1e30f;
#pragma unroll
        for (int dy = -1; dy <= 1; dy++)
#pragma unroll
            for (int dx = -1; dx <= 1; dx++) {
                int hh = h + dy, ww2 = w + dx;
                if (hh >= 0 && hh < HH && ww2 >= 0 && ww2 < WW)
                    mx = fmaxf(mx, alive[hh * WW + ww2]);
            }
        scl[tid] = (mx > 0.1f ? 1.f : 0.f) * (float)mask[p];
    }

    float acc[4][4] = {};
    const float* Yb = g_y + (size_t)b * M1 * HWp + nt * BN2;
    const float* Lw = lnw + nt * BN2;
    const float* Lb = lnb + nt * BN2;

    for (int k0 = 0; k0 < M1; k0 += BK2) {
        // A: w2 tile 64x32, transposed into As[k][m]
#pragma unroll
        for (int i = 0; i < 2; i++) {
            int f4i = tid + i * 256;        // 0..511
            int r   = f4i >> 3;             // 0..63
            int cc  = (f4i & 7) * 4;        // 0..28
            float4 a = *reinterpret_cast<const float4*>(w2 + r * M1 + k0 + cc);
            As[cc + 0][r] = a.x;
            As[cc + 1][r] = a.y;
            As[cc + 2][r] = a.z;
            As[cc + 3][r] = a.w;
        }
        // B: relu(LN(Y)) tile 32x64
#pragma unroll
        for (int i = 0; i < 2; i++) {
            int f4i = tid + i * 256;
            int r   = f4i >> 4;             // 0..31
            int cc  = (f4i & 15) * 4;
            size_t off = (size_t)(k0 + r) * HWp + cc;
            float4 yv = *reinterpret_cast<const float4*>(Yb + off);
            float4 wv = *reinterpret_cast<const float4*>(Lw + off);
            float4 bv = *reinterpret_cast<const float4*>(Lb + off);
            float4 r4;
            r4.x = fmaxf((yv.x - mu) * rstd * wv.x + bv.x, 0.f);
            r4.y = fmaxf((yv.y - mu) * rstd * wv.y + bv.y, 0.f);
            r4.z = fmaxf((yv.z - mu) * rstd * wv.z + bv.z, 0.f);
            r4.w = fmaxf((yv.w - mu) * rstd * wv.w + bv.w, 0.f);
            *reinterpret_cast<float4*>(&Bs[r][cc]) = r4;
        }
        __syncthreads();
#pragma unroll
        for (int k = 0; k < BK2; k++) {
            float ra[4], rb[4];
#pragma unroll
            for (int i = 0; i < 4; i++) ra[i] = As[k][ty * 4 + i];
#pragma unroll
            for (int j = 0; j < 4; j++) rb[j] = Bs[k][tx * 4 + j];
#pragma unroll
            for (int i = 0; i < 4; i++)
#pragma unroll
                for (int j = 0; j < 4; j++) acc[i][j] += ra[i] * rb[j];
        }
        __syncthreads();
    }

    // epilogue: out = state + z * scale
    const float* Sb = state + (size_t)b * CC * HWp + nt * BN2;
    float* Ob = out + (size_t)b * CC * HWp + nt * BN2;
#pragma unroll
    for (int i = 0; i < 4; i++) {
        int m = ty * 4 + i;
        size_t off = (size_t)m * HWp + tx * 4;
        float4 sv = *reinterpret_cast<const float4*>(Sb + off);
        float4 ov;
        ov.x = sv.x + acc[i][0] * scl[tx * 4 + 0];
        ov.y = sv.y + acc[i][1] * scl[tx * 4 + 1];
        ov.z = sv.z + acc[i][2] * scl[tx * 4 + 2];
        ov.w = sv.w + acc[i][3] * scl[tx * 4 + 3];
        *reinterpret_cast<float4*>(Ob + off) = ov;
    }
}

// ---------------------------------------------------------------------------
extern "C" void kernel_launch(void* const* d_in, const int* in_sizes, int n_in,
                              void* d_out, int out_size) {
    const float* state = (const float*)d_in[0];
    const float* w1    = (const float*)d_in[1];
    const float* lnw   = (const float*)d_in[2];
    const float* lnb   = (const float*)d_in[3];
    const float* w2    = (const float*)d_in[4];
    const int*   mask  = (const int*)d_in[5];
    float* out = (float*)d_out;

    perc_kernel<<<(BB * CC * HWp) / 256, 256>>>(state);
    gemm1_kernel<<<dim3(25, 4, BB), 256>>>(w1);
    stats_kernel<<<1, 128>>>();
    gemm2_kernel<<<dim3(25, 1, BB), 256>>>(w2, lnw, lnb, state, mask, out);
}